// round 15
// baseline (speedup 1.0000x reference)
#include <cuda_runtime.h>
#include <cuda_bf16.h>
#include <cstdint>

// MissHitScatter: inputs [N=65536, D=1024] f32 -> out [P=4, N, D] f32.
// slice 0 = copy of input, slices 1..3 = zeros. 1.25 GiB total traffic.
//
// R14: persistent one-wave grid-stride variant of the converged champion.
// Same contiguous 32 KB chunks, same global chunk order (copy chunks first,
// then pure-zero chunks), same batched __ldg (MLP=8) + __stwt streaming
// stores. Only change: each block processes chunks b, b+G, b+2G, ... so
// there are zero wave transitions and LDG/STG queues stay primed.

#define V 8          // float4 per thread; chunk = 256*V float4 = 32 KB
#define TPB 256

__global__ void __launch_bounds__(TPB) misshit_scatter_kernel(
    const float4* __restrict__ in, float4* __restrict__ out,
    size_t n4, size_t n_chunks)
{
    const size_t chunk_f4 = (size_t)TPB * V;
    const float4 z = make_float4(0.f, 0.f, 0.f, 0.f);

    for (size_t c = blockIdx.x; c < n_chunks; c += gridDim.x) {
        size_t base = c * chunk_f4 + threadIdx.x;

        if (base + (size_t)(V - 1) * TPB < n4) {
            // Pure copy chunk: batch all loads first (MLP=V).
            float4 v[V];
#pragma unroll
            for (int j = 0; j < V; j++)
                v[j] = __ldg(in + base + (size_t)j * TPB);
#pragma unroll
            for (int j = 0; j < V; j++)
                __stwt(out + base + (size_t)j * TPB, v[j]);
        } else if (base >= n4) {
            // Pure zero chunk: streaming stores only.
#pragma unroll
            for (int j = 0; j < V; j++)
                __stwt(out + base + (size_t)j * TPB, z);
        } else {
            // Boundary straddle (not taken: n4 = 16Mi is a multiple of 2048).
#pragma unroll
            for (int j = 0; j < V; j++) {
                size_t i = base + (size_t)j * TPB;
                float4 v = (i < n4) ? __ldg(in + i) : z;
                __stwt(out + i, v);
            }
        }
    }
}

extern "C" void kernel_launch(void* const* d_in, const int* in_sizes, int n_in,
                              void* d_out, int out_size) {
    const size_t n_elems = (size_t)in_sizes[0];   // 65536 * 1024 floats
    const size_t n4 = n_elems / 4;                // float4 per slice
    const size_t total4 = n4 * 4;
    const size_t chunk_f4 = (size_t)TPB * V;      // 2048 float4 = 32 KB
    const size_t n_chunks = (total4 + chunk_f4 - 1) / chunk_f4;  // 32768

    // One-wave persistent grid: blocks/SM at regs=32, 256 thr => 6 resident
    // (observed 74.5% occ = 48/64 warps). 148 SMs (152 on GB300; min is safe).
    int dev = 0, sms = 148, bps = 0;
    cudaGetDevice(&dev);
    cudaDeviceGetAttribute(&sms, cudaDevAttrMultiProcessorCount, dev);
    cudaOccupancyMaxActiveBlocksPerMultiprocessor(
        &bps, misshit_scatter_kernel, TPB, 0);
    if (bps < 1) bps = 1;
    size_t grid = (size_t)sms * bps;
    if (grid > n_chunks) grid = n_chunks;

    misshit_scatter_kernel<<<(unsigned)grid, TPB>>>(
        (const float4*)d_in[0], (float4*)d_out, n4, n_chunks);
}

// round 16
// speedup vs baseline: 1.2402x; 1.2402x over previous
#include <cuda_runtime.h>
#include <cuda_bf16.h>
#include <cstdint>

// MissHitScatter: inputs [N=65536, D=1024] f32 -> out [P=4, N, D] f32.
// slice 0 = copy of input, slices 1..3 = zeros. 1.25 GiB total traffic.
//
// FINAL CONVERGED KERNEL (R3 structure; reproduced 5x at 177.0-177.7 us
// kernel, 91.0-91.4% DRAM, 7.21-7.25 TB/s = ~90.5% of 8 TB/s HBM spec):
//   - 8 x float4 per thread, contiguous 32 KB per-block spans
//   - batched __ldg loads (MLP=8) before __stwt streaming stores
//   - copy blocks front-loaded, then a long pure-write phase at near-peak BW
//   - independent blocks (NOT persistent) keep LDG/STG queues full via
//     cross-block overlap
// Exhaustively probed and rejected: per-warp multi-stream stores (-10%),
// wave-interleaved block types (-9%), __ldcs (-18%), V=16 (-1.4%),
// 256-bit ld/st.v8 (neutral), persistent grid-stride (-19%). Residual ~9%
// is HBM read/write turnaround + ramp — below the kernel-addressable line.

#define V 8  // float4 per thread

__global__ void __launch_bounds__(256) misshit_scatter_kernel(
    const float4* __restrict__ in, float4* __restrict__ out, size_t n4)
{
    // Each block covers a contiguous span of 256*V float4s; within each of the
    // V sub-iterations accesses are warp-coalesced (stride = blockDim).
    size_t base = (size_t)blockIdx.x * (blockDim.x * V) + threadIdx.x;

    if (base + (size_t)(V - 1) * blockDim.x < n4) {
        // Entirely inside the copy slice: batch all loads first (MLP=V).
        float4 v[V];
#pragma unroll
        for (int j = 0; j < V; j++)
            v[j] = __ldg(in + base + (size_t)j * blockDim.x);
#pragma unroll
        for (int j = 0; j < V; j++)
            __stwt(out + base + (size_t)j * blockDim.x, v[j]);
    } else if (base >= n4) {
        // Entirely inside the zero slices: pure streaming stores.
        const float4 z = make_float4(0.f, 0.f, 0.f, 0.f);
#pragma unroll
        for (int j = 0; j < V; j++) {
            size_t i = base + (size_t)j * blockDim.x;
            __stwt(out + i, z);
        }
    } else {
        // Straddles the copy/zero boundary (not taken for this shape:
        // n4 = 16Mi float4 is a multiple of 256*V = 2048).
        const float4 z = make_float4(0.f, 0.f, 0.f, 0.f);
#pragma unroll
        for (int j = 0; j < V; j++) {
            size_t i = base + (size_t)j * blockDim.x;
            float4 v = (i < n4) ? __ldg(in + i) : z;
            __stwt(out + i, v);
        }
    }
}

extern "C" void kernel_launch(void* const* d_in, const int* in_sizes, int n_in,
                              void* d_out, int out_size) {
    const size_t n_elems = (size_t)in_sizes[0];   // 65536 * 1024 floats
    const size_t n4 = n_elems / 4;                // float4 per slice
    const size_t total4 = n4 * 4;                 // float4 in full output

    const int threads = 256;
    const size_t per_block = (size_t)threads * V;
    const int blocks = (int)((total4 + per_block - 1) / per_block);  // 32768

    misshit_scatter_kernel<<<blocks, threads>>>(
        (const float4*)d_in[0], (float4*)d_out, n4);
}